// round 14
// baseline (speedup 1.0000x reference)
#include <cuda_runtime.h>
#include <math.h>

#define D_MODEL   1024
#define SEQ_LEN   32768
#define NBLK_A    512                   // phase-A blocks
#define LPB       64                    // l's per block
#define LPW       8                     // l's per warp (8 warps/block)

#define TWO_PI    6.283185307179586f
#define INV_2PI   0.15915494309189535f
#define MAGIC     12582912.0f           // 1.5 * 2^23
#define C1_2PI    6.28318548202514648f  // fl32(2*pi)
#define INV1023   (1.0f / 1023.0f)
#define FIX_SCALE 268435456.0f          // 2^28
#define FIX_INV   3.725290298461914e-9f // 2^-28

typedef unsigned long long ull;

// Scratch (device globals; zero-initialized; no allocation in kernel_launch)
// g_sigint[j]: fixed-point signal accumulator; j = 2*i + h where i = m*32+k
// packs d = 32k+2m+h, sign-twisted by sigma_m. Finalizer block converts,
// unmaps sigma, writes g_signal, and re-zeroes for the next graph replay.
__device__ long long g_sigint[D_MODEL];
__device__ __align__(16) float g_signal[D_MODEL];
__device__ unsigned g_done = 0;

// ---------------- packed f32x2 helpers --------------------------------------
__device__ __forceinline__ ull fma2(ull a, ull b, ull c) {
    ull d; asm("fma.rn.f32x2 %0,%1,%2,%3;" : "=l"(d) : "l"(a), "l"(b), "l"(c)); return d;
}
__device__ __forceinline__ ull add2(ull a, ull b) {
    ull d; asm("add.rn.f32x2 %0,%1,%2;" : "=l"(d) : "l"(a), "l"(b)); return d;
}
__device__ __forceinline__ ull pk2(float lo, float hi) {
    ull d; asm("mov.b64 %0,{%1,%2};" : "=l"(d) : "f"(lo), "f"(hi)); return d;
}
__device__ __forceinline__ float2 unpk(ull v) {
    float2 r; asm("mov.b64 {%0,%1},%2;" : "=f"(r.x), "=f"(r.y) : "l"(v)); return r;
}

// ---------------------------------------------------------------------------
// Kernel A: packed-pair Chebyshev recurrence over d, TWO interleaved l-chains
// per iteration. Lane k owns d=32k..32k+31 as 16 packed pairs.
// Epilogue: block partials -> fixed-point atomicAdd (order-independent =
// deterministic); LAST block converts to float signal and resets state.
// ---------------------------------------------------------------------------
__global__ void __launch_bounds__(256, 4)
sinsum_kernel(const float* __restrict__ inputs) {
    __shared__ float4 co[LPB];        // (a, a*log1p(l), 2cos(dl), 2cos(2dl))
    __shared__ ull    sred[8 * 512];  // 32KB packed cross-warp buffer
    __shared__ unsigned s_last;

    const int tid = threadIdx.x;
    const int w   = tid >> 5;
    const int k   = tid & 31;

    if (tid < LPB) {
        const int l = blockIdx.x * LPB + tid;
        float x  = inputs[l];
        float a  = TWO_PI * x;
        float p  = log1pf((float)l);
        float dl = a * INV1023;
        float d2 = dl * dl;
        float u2 = 4.0f * d2;                         // (2*dl)^2
        float c  = fmaf(d2, fmaf(d2, fmaf(d2, -(1.0f/360.0f), (1.0f/12.0f)), -1.0f), 2.0f);
        float c2 = fmaf(u2, fmaf(u2, fmaf(u2, -(1.0f/360.0f), (1.0f/12.0f)), -1.0f), 2.0f);
        co[tid]  = make_float4(a, a * p, c, c2);
    }
    __syncthreads();

    const float tk = (float)(32 * k) * INV1023;

    ull acc[16];
#pragma unroll
    for (int m = 0; m < 16; ++m) acc[m] = 0ull;

#pragma unroll 1
    for (int jp = 0; jp < LPW / 2; ++jp) {
        float4 CA = co[w * LPW + 2 * jp];
        float4 CB = co[w * LPW + 2 * jp + 1];

        // --- seeds for chain A and chain B (independent) ---
        float phiA = fmaf(CA.x, tk, CA.y);
        float phiB = fmaf(CB.x, tk, CB.y);
        float yA   = fmaf(phiA, INV_2PI, MAGIC);
        float yB   = fmaf(phiB, INV_2PI, MAGIC);
        float rA   = fmaf(yA - MAGIC, -C1_2PI, phiA);
        float rB   = fmaf(yB - MAGIC, -C1_2PI, phiB);
        float dlA  = CA.x * INV1023;
        float dlB  = CB.x * INV1023;
        float sA0  = __sinf(rA);
        float sB0  = __sinf(rB);
        float sA1  = __sinf(rA + dlA);
        float sB1  = __sinf(rB + dlB);
        float sA2  = fmaf(CA.z, sA1, -sA0);
        float sB2  = fmaf(CB.z, sB1, -sB0);
        float sA3  = fmaf(CA.z, sA2, -sA1);
        float sB3  = fmaf(CB.z, sB2, -sB1);

        ull a0 = pk2(sA0, sA1), a1 = pk2(sA2, sA3);
        ull b0 = pk2(sB0, sB1), b1 = pk2(sB2, sB3);
        ull cAp = pk2(CA.w, CA.w), cAn = pk2(-CA.w, -CA.w);
        ull cBp = pk2(CB.w, CB.w), cBn = pk2(-CB.w, -CB.w);

        acc[0] = add2(acc[0], add2(a0, b0));
        acc[1] = add2(acc[1], add2(a1, b1));

#pragma unroll
        for (int m = 2; m < 16; ++m) {
            // sign-twisted: a_m = fma2(m odd ? +c2 : -c2, a_{m-1}, a_{m-2})
            ull an = fma2((m & 1) ? cAp : cAn, a1, a0);
            ull bn = fma2((m & 1) ? cBp : cBn, b1, b0);
            acc[m] = add2(acc[m], add2(an, bn));
            a0 = a1; a1 = an;
            b0 = b1; b1 = bn;
        }
    }

    // ---- Epilogue: cross-warp smem reduce -> fixed-point atomics ----------
#pragma unroll
    for (int m = 0; m < 16; ++m)
        sred[w * 512 + m * 32 + k] = acc[m];
    __syncthreads();

#pragma unroll
    for (int rep = 0; rep < 2; ++rep) {
        const int i = tid + rep * 256;
        ull s = sred[i];
#pragma unroll
        for (int ww = 1; ww < 8; ++ww)
            s = add2(s, sred[ww * 512 + i]);
        float2 v = unpk(s);
        atomicAdd((ull*)&g_sigint[2 * i],
                  (ull)(long long)__float2ll_rn(v.x * FIX_SCALE));
        atomicAdd((ull*)&g_sigint[2 * i + 1],
                  (ull)(long long)__float2ll_rn(v.y * FIX_SCALE));
    }

    // ---- last-block finalize (also resets state for next graph replay) ---
    __threadfence();
    __syncthreads();
    if (tid == 0)
        s_last = (atomicAdd(&g_done, 1u) == NBLK_A - 1) ? 1u : 0u;
    __syncthreads();

    if (s_last) {
#pragma unroll
        for (int rep = 0; rep < 4; ++rep) {
            const int j = tid + rep * 256;            // 0..1023
            long long raw = *(volatile long long*)&g_sigint[j];
            const int i = j >> 1, h = j & 1;
            const int m = i >> 5, kk = i & 31;
            const float sg = ((m >> 1) & 1) ? -1.0f : 1.0f;  // undo sigma_m
            g_signal[32 * kk + 2 * m + h] = sg * ((float)raw * FIX_INV);
            *(volatile long long*)&g_sigint[j] = 0ll;
        }
        __threadfence();
        if (tid == 0) g_done = 0;
    }
}

// ---------------------------------------------------------------------------
// Kernel C: GEMV out = signal @ W^T + b. 256 blocks x 128 thr, warp per row.
// ---------------------------------------------------------------------------
__global__ void __launch_bounds__(128)
gemv_kernel(const float* __restrict__ W, const float* __restrict__ bias,
            float* __restrict__ out) {
    __shared__ __align__(16) float ssig[D_MODEL];

    const int tid = threadIdx.x;
#pragma unroll
    for (int i = tid; i < D_MODEL / 4; i += 128)
        ((float4*)ssig)[i] = ((const float4*)g_signal)[i];
    __syncthreads();

    const int warp = tid >> 5;
    const int lane = tid & 31;
    const int row  = blockIdx.x * 4 + warp;

    const float4* w4 = (const float4*)(W + row * D_MODEL);
    float acc = 0.0f;
#pragma unroll
    for (int kk = lane; kk < D_MODEL / 4; kk += 32) {
        float4 wv = w4[kk];
        float4 sv = ((const float4*)ssig)[kk];
        acc = fmaf(wv.x, sv.x, acc);
        acc = fmaf(wv.y, sv.y, acc);
        acc = fmaf(wv.z, sv.z, acc);
        acc = fmaf(wv.w, sv.w, acc);
    }
#pragma unroll
    for (int off = 16; off > 0; off >>= 1)
        acc += __shfl_down_sync(0xffffffffu, acc, off);

    if (lane == 0) out[row] = acc + bias[row];
}

// ---------------------------------------------------------------------------
extern "C" void kernel_launch(void* const* d_in, const int* in_sizes, int n_in,
                              void* d_out, int out_size) {
    const float* inputs = (const float*)d_in[0];   // [32768]
    const float* W      = (const float*)d_in[1];   // [1024,1024]
    const float* b      = (const float*)d_in[2];   // [1024]
    float*       out    = (float*)d_out;           // [1024]

    sinsum_kernel<<<NBLK_A, 256>>>(inputs);
    gemv_kernel<<<D_MODEL / 4, 128>>>(W, b, out);
    (void)in_sizes; (void)n_in; (void)out_size;
}

// round 15
// speedup vs baseline: 1.9435x; 1.9435x over previous
#include <cuda_runtime.h>
#include <math.h>

#define D_MODEL   1024
#define SEQ_LEN   32768
#define NBLK_A    512                   // phase-A blocks
#define LPB       64                    // l's per block
#define LPW       8                     // l's per warp (8 warps/block)

#define TWO_PI    6.283185307179586f
#define INV_2PI   0.15915494309189535f
#define MAGIC     12582912.0f           // 1.5 * 2^23
#define C1_2PI    6.28318548202514648f  // fl32(2*pi)
#define INV1023   (1.0f / 1023.0f)

typedef unsigned long long ull;

// Scratch (device globals; no allocation in kernel_launch)
// g_part[slice][col]; col i = m*32+k packs d=(32k+2m, 32k+2m+1),
// sign-twisted by sigma_m. A stores coalesced (STG.64, 4KB/warp row).
__device__ ull g_part[NBLK_A * 512];               // 2 MB
__device__ __align__(16) float g_signal[D_MODEL];

// ---------------- packed f32x2 helpers --------------------------------------
__device__ __forceinline__ ull fma2(ull a, ull b, ull c) {
    ull d; asm("fma.rn.f32x2 %0,%1,%2,%3;" : "=l"(d) : "l"(a), "l"(b), "l"(c)); return d;
}
__device__ __forceinline__ ull add2(ull a, ull b) {
    ull d; asm("add.rn.f32x2 %0,%1,%2;" : "=l"(d) : "l"(a), "l"(b)); return d;
}
__device__ __forceinline__ ull pk2(float lo, float hi) {
    ull d; asm("mov.b64 %0,{%1,%2};" : "=l"(d) : "f"(lo), "f"(hi)); return d;
}
__device__ __forceinline__ float2 unpk(ull v) {
    float2 r; asm("mov.b64 {%0,%1},%2;" : "=f"(r.x), "=f"(r.y) : "l"(v)); return r;
}

// ---------------------------------------------------------------------------
// Kernel A: packed-pair Chebyshev recurrence over d, TWO interleaved l-chains
// per iteration for ILP. Lane k owns d=32k..32k+31 as 16 packed pairs.
// (R13-measured structure: coalesced epilogue store, 7.62us.)
// ---------------------------------------------------------------------------
__global__ void __launch_bounds__(256, 4)
sinsum_kernel(const float* __restrict__ inputs) {
    __shared__ float4 co[LPB];        // (a, a*log1p(l), 2cos(dl), 2cos(2dl))
    __shared__ ull    sred[8 * 512];  // 32KB packed cross-warp buffer

    const int tid = threadIdx.x;
    const int w   = tid >> 5;
    const int k   = tid & 31;

    if (tid < LPB) {
        const int l = blockIdx.x * LPB + tid;
        float x  = inputs[l];
        float a  = TWO_PI * x;
        float p  = log1pf((float)l);
        float dl = a * INV1023;
        float d2 = dl * dl;
        float u2 = 4.0f * d2;                         // (2*dl)^2
        float c  = fmaf(d2, fmaf(d2, fmaf(d2, -(1.0f/360.0f), (1.0f/12.0f)), -1.0f), 2.0f);
        float c2 = fmaf(u2, fmaf(u2, fmaf(u2, -(1.0f/360.0f), (1.0f/12.0f)), -1.0f), 2.0f);
        co[tid]  = make_float4(a, a * p, c, c2);
    }
    __syncthreads();

    const float tk = (float)(32 * k) * INV1023;

    ull acc[16];
#pragma unroll
    for (int m = 0; m < 16; ++m) acc[m] = 0ull;

#pragma unroll 1
    for (int jp = 0; jp < LPW / 2; ++jp) {
        float4 CA = co[w * LPW + 2 * jp];
        float4 CB = co[w * LPW + 2 * jp + 1];

        // --- seeds for chain A and chain B (independent) ---
        float phiA = fmaf(CA.x, tk, CA.y);
        float phiB = fmaf(CB.x, tk, CB.y);
        float yA   = fmaf(phiA, INV_2PI, MAGIC);
        float yB   = fmaf(phiB, INV_2PI, MAGIC);
        float rA   = fmaf(yA - MAGIC, -C1_2PI, phiA);
        float rB   = fmaf(yB - MAGIC, -C1_2PI, phiB);
        float dlA  = CA.x * INV1023;
        float dlB  = CB.x * INV1023;
        float sA0  = __sinf(rA);
        float sB0  = __sinf(rB);
        float sA1  = __sinf(rA + dlA);
        float sB1  = __sinf(rB + dlB);
        float sA2  = fmaf(CA.z, sA1, -sA0);
        float sB2  = fmaf(CB.z, sB1, -sB0);
        float sA3  = fmaf(CA.z, sA2, -sA1);
        float sB3  = fmaf(CB.z, sB2, -sB1);

        ull a0 = pk2(sA0, sA1), a1 = pk2(sA2, sA3);
        ull b0 = pk2(sB0, sB1), b1 = pk2(sB2, sB3);
        ull cAp = pk2(CA.w, CA.w), cAn = pk2(-CA.w, -CA.w);
        ull cBp = pk2(CB.w, CB.w), cBn = pk2(-CB.w, -CB.w);

        acc[0] = add2(acc[0], add2(a0, b0));
        acc[1] = add2(acc[1], add2(a1, b1));

#pragma unroll
        for (int m = 2; m < 16; ++m) {
            // sign-twisted: a_m = fma2(m odd ? +c2 : -c2, a_{m-1}, a_{m-2})
            ull an = fma2((m & 1) ? cAp : cAn, a1, a0);
            ull bn = fma2((m & 1) ? cBp : cBn, b1, b0);
            acc[m] = add2(acc[m], add2(an, bn));
            a0 = a1; a1 = an;
            b0 = b1; b1 = bn;
        }
    }

    // Epilogue: packed cross-warp reduce, coalesced store.
#pragma unroll
    for (int m = 0; m < 16; ++m)
        sred[w * 512 + m * 32 + k] = acc[m];
    __syncthreads();

#pragma unroll
    for (int rep = 0; rep < 2; ++rep) {
        const int i = tid + rep * 256;
        ull s = sred[i];
#pragma unroll
        for (int ww = 1; ww < 8; ++ww)
            s = add2(s, sred[ww * 512 + i]);
        g_part[blockIdx.x * 512 + i] = s;             // STG.64 coalesced
    }
}

// ---------------------------------------------------------------------------
// Kernel B: reduce 512 slices per packed column. 128 blocks x 256 threads.
// Block b owns cols 4b..4b+3 (same m = b>>3). Thread (sp = t>>2, c = t&3)
// sums slices sp, sp+64, ..., 8 each; warp load = 8 full 32B sectors.
// Flat smem tree (strides 128..4) then sigma-unmap, write signal.
// ---------------------------------------------------------------------------
__global__ void __launch_bounds__(256)
reduce_kernel() {
    __shared__ ull sm[256];
    const int tid = threadIdx.x;
    const int b   = blockIdx.x;
    const int sp  = tid >> 2;
    const int c   = tid & 3;
    const int col = 4 * b + c;

    ull s = 0ull;
#pragma unroll
    for (int j = 0; j < 8; ++j)
        s = add2(s, g_part[(sp + 64 * j) * 512 + col]);
    sm[tid] = s;
    __syncthreads();

#pragma unroll
    for (int step = 128; step >= 4; step >>= 1) {
        if (tid < step)
            sm[tid] = add2(sm[tid], sm[tid + step]);
        __syncthreads();
    }

    if (tid < 4) {
        const int cc = 4 * b + tid;
        const int m  = cc >> 5;
        const int kk = cc & 31;
        const float sg = ((m >> 1) & 1) ? -1.0f : 1.0f;   // undo sigma_m
        float2 v = unpk(sm[tid]);
        const int d0 = 32 * kk + 2 * m;
        g_signal[d0]     = sg * v.x;
        g_signal[d0 + 1] = sg * v.y;
    }
}

// ---------------------------------------------------------------------------
// Kernel C: GEMV out = signal @ W^T + b. 256 blocks x 128 thr, warp per row.
// ---------------------------------------------------------------------------
__global__ void __launch_bounds__(128)
gemv_kernel(const float* __restrict__ W, const float* __restrict__ bias,
            float* __restrict__ out) {
    __shared__ __align__(16) float ssig[D_MODEL];

    const int tid = threadIdx.x;
#pragma unroll
    for (int i = tid; i < D_MODEL / 4; i += 128)
        ((float4*)ssig)[i] = ((const float4*)g_signal)[i];
    __syncthreads();

    const int warp = tid >> 5;
    const int lane = tid & 31;
    const int row  = blockIdx.x * 4 + warp;

    const float4* w4 = (const float4*)(W + row * D_MODEL);
    float acc = 0.0f;
#pragma unroll
    for (int kk = lane; kk < D_MODEL / 4; kk += 32) {
        float4 wv = w4[kk];
        float4 sv = ((const float4*)ssig)[kk];
        acc = fmaf(wv.x, sv.x, acc);
        acc = fmaf(wv.y, sv.y, acc);
        acc = fmaf(wv.z, sv.z, acc);
        acc = fmaf(wv.w, sv.w, acc);
    }
#pragma unroll
    for (int off = 16; off > 0; off >>= 1)
        acc += __shfl_down_sync(0xffffffffu, acc, off);

    if (lane == 0) out[row] = acc + bias[row];
}

// ---------------------------------------------------------------------------
extern "C" void kernel_launch(void* const* d_in, const int* in_sizes, int n_in,
                              void* d_out, int out_size) {
    const float* inputs = (const float*)d_in[0];   // [32768]
    const float* W      = (const float*)d_in[1];   // [1024,1024]
    const float* b      = (const float*)d_in[2];   // [1024]
    float*       out    = (float*)d_out;           // [1024]

    sinsum_kernel<<<NBLK_A, 256>>>(inputs);
    reduce_kernel<<<128, 256>>>();
    gemv_kernel<<<D_MODEL / 4, 128>>>(W, b, out);
    (void)in_sizes; (void)n_in; (void)out_size;
}

// round 16
// speedup vs baseline: 1.9483x; 1.0025x over previous
#include <cuda_runtime.h>
#include <math.h>

#define D_MODEL   1024
#define SEQ_LEN   32768
#define NBLK_A    1024                  // phase-A blocks (128 thr each)
#define LPB       32                    // l's per block
#define LPW       8                     // l's per warp (4 warps/block)

#define TWO_PI    6.283185307179586f
#define INV_2PI   0.15915494309189535f
#define MAGIC     12582912.0f           // 1.5 * 2^23
#define C1_2PI    6.28318548202514648f  // fl32(2*pi)
#define INV1023   (1.0f / 1023.0f)

typedef unsigned long long ull;

// Scratch (device globals; no allocation in kernel_launch)
// g_part[slice][col]; col i = m*32+k packs d=(32k+2m, 32k+2m+1),
// sign-twisted by sigma_m. A stores coalesced (STG.64).
__device__ ull g_part[NBLK_A * 512];               // 4 MB
__device__ __align__(16) float g_signal[D_MODEL];

// ---------------- packed f32x2 helpers --------------------------------------
__device__ __forceinline__ ull fma2(ull a, ull b, ull c) {
    ull d; asm("fma.rn.f32x2 %0,%1,%2,%3;" : "=l"(d) : "l"(a), "l"(b), "l"(c)); return d;
}
__device__ __forceinline__ ull add2(ull a, ull b) {
    ull d; asm("add.rn.f32x2 %0,%1,%2;" : "=l"(d) : "l"(a), "l"(b)); return d;
}
__device__ __forceinline__ ull pk2(float lo, float hi) {
    ull d; asm("mov.b64 %0,{%1,%2};" : "=l"(d) : "f"(lo), "f"(hi)); return d;
}
__device__ __forceinline__ float2 unpk(ull v) {
    float2 r; asm("mov.b64 {%0,%1},%2;" : "=f"(r.x), "=f"(r.y) : "l"(v)); return r;
}

// ---------------------------------------------------------------------------
// Kernel A: packed-pair Chebyshev recurrence over d, TWO interleaved l-chains
// per iteration. Lane k owns d=32k..32k+31 as 16 packed pairs.
// 128-thread blocks x 1024 grid: 8 blocks/SM, ~1.4% wave imbalance
// (vs 15% at 512x256). Two-phase epilogue keeps smem at ~8.8KB.
// ---------------------------------------------------------------------------
__global__ void __launch_bounds__(128, 8)
sinsum_kernel(const float* __restrict__ inputs) {
    __shared__ float4 co[LPB];        // (a, a*log1p(l), 2cos(dl), 2cos(2dl))
    __shared__ ull    sred[2 * 512];  // 8KB two-phase epilogue buffer

    const int tid = threadIdx.x;
    const int w   = tid >> 5;         // 0..3
    const int k   = tid & 31;

    if (tid < LPB) {
        const int l = blockIdx.x * LPB + tid;
        float x  = inputs[l];
        float a  = TWO_PI * x;
        float p  = log1pf((float)l);
        float dl = a * INV1023;
        float d2 = dl * dl;
        float u2 = 4.0f * d2;                         // (2*dl)^2
        float c  = fmaf(d2, fmaf(d2, fmaf(d2, -(1.0f/360.0f), (1.0f/12.0f)), -1.0f), 2.0f);
        float c2 = fmaf(u2, fmaf(u2, fmaf(u2, -(1.0f/360.0f), (1.0f/12.0f)), -1.0f), 2.0f);
        co[tid]  = make_float4(a, a * p, c, c2);
    }
    __syncthreads();

    const float tk = (float)(32 * k) * INV1023;

    ull acc[16];
#pragma unroll
    for (int m = 0; m < 16; ++m) acc[m] = 0ull;

#pragma unroll 1
    for (int jp = 0; jp < LPW / 2; ++jp) {
        float4 CA = co[w * LPW + 2 * jp];
        float4 CB = co[w * LPW + 2 * jp + 1];

        // --- seeds for chain A and chain B (independent) ---
        float phiA = fmaf(CA.x, tk, CA.y);
        float phiB = fmaf(CB.x, tk, CB.y);
        float yA   = fmaf(phiA, INV_2PI, MAGIC);
        float yB   = fmaf(phiB, INV_2PI, MAGIC);
        float rA   = fmaf(yA - MAGIC, -C1_2PI, phiA);
        float rB   = fmaf(yB - MAGIC, -C1_2PI, phiB);
        float dlA  = CA.x * INV1023;
        float dlB  = CB.x * INV1023;
        float sA0  = __sinf(rA);
        float sB0  = __sinf(rB);
        float sA1  = __sinf(rA + dlA);
        float sB1  = __sinf(rB + dlB);
        float sA2  = fmaf(CA.z, sA1, -sA0);
        float sB2  = fmaf(CB.z, sB1, -sB0);
        float sA3  = fmaf(CA.z, sA2, -sA1);
        float sB3  = fmaf(CB.z, sB2, -sB1);

        ull a0 = pk2(sA0, sA1), a1 = pk2(sA2, sA3);
        ull b0 = pk2(sB0, sB1), b1 = pk2(sB2, sB3);
        ull cAp = pk2(CA.w, CA.w), cAn = pk2(-CA.w, -CA.w);
        ull cBp = pk2(CB.w, CB.w), cBn = pk2(-CB.w, -CB.w);

        acc[0] = add2(acc[0], add2(a0, b0));
        acc[1] = add2(acc[1], add2(a1, b1));

#pragma unroll
        for (int m = 2; m < 16; ++m) {
            // sign-twisted: a_m = fma2(m odd ? +c2 : -c2, a_{m-1}, a_{m-2})
            ull an = fma2((m & 1) ? cAp : cAn, a1, a0);
            ull bn = fma2((m & 1) ? cBp : cBn, b1, b0);
            acc[m] = add2(acc[m], add2(an, bn));
            a0 = a1; a1 = an;
            b0 = b1; b1 = bn;
        }
    }

    // Epilogue phase 1: warps 2,3 stage.
    if (w >= 2) {
#pragma unroll
        for (int m = 0; m < 16; ++m)
            sred[(w - 2) * 512 + m * 32 + k] = acc[m];
    }
    __syncthreads();
    // Phase 2: warps 0,1 add in place.
    if (w < 2) {
#pragma unroll
        for (int m = 0; m < 16; ++m) {
            const int i = w * 512 + m * 32 + k;
            sred[i] = add2(sred[i], acc[m]);
        }
    }
    __syncthreads();

    // Gather 2 segments, coalesced store.
#pragma unroll
    for (int rep = 0; rep < 4; ++rep) {
        const int i = tid + rep * 128;
        ull s = add2(sred[i], sred[512 + i]);
        g_part[blockIdx.x * 512 + i] = s;             // STG.64 coalesced
    }
}

// ---------------------------------------------------------------------------
// Kernel B: reduce 1024 slices per packed column. 128 blocks x 256 threads.
// Block b owns cols 4b..4b+3. Thread (sp = t>>2, c = t&3) sums slices
// sp + 64*j, j<16; warp load = 8 full 32B sectors. Flat smem tree,
// sigma-unmap, write signal.
// ---------------------------------------------------------------------------
__global__ void __launch_bounds__(256)
reduce_kernel() {
    __shared__ ull sm[256];
    const int tid = threadIdx.x;
    const int b   = blockIdx.x;
    const int sp  = tid >> 2;
    const int c   = tid & 3;
    const int col = 4 * b + c;

    ull s = 0ull;
#pragma unroll
    for (int j = 0; j < 16; ++j)
        s = add2(s, g_part[(sp + 64 * j) * 512 + col]);
    sm[tid] = s;
    __syncthreads();

#pragma unroll
    for (int step = 128; step >= 4; step >>= 1) {
        if (tid < step)
            sm[tid] = add2(sm[tid], sm[tid + step]);
        __syncthreads();
    }

    if (tid < 4) {
        const int cc = 4 * b + tid;
        const int m  = cc >> 5;
        const int kk = cc & 31;
        const float sg = ((m >> 1) & 1) ? -1.0f : 1.0f;   // undo sigma_m
        float2 v = unpk(sm[tid]);
        const int d0 = 32 * kk + 2 * m;
        g_signal[d0]     = sg * v.x;
        g_signal[d0 + 1] = sg * v.y;
    }
}

// ---------------------------------------------------------------------------
// Kernel C: GEMV out = signal @ W^T + b. 256 blocks x 128 thr, warp per row.
// ---------------------------------------------------------------------------
__global__ void __launch_bounds__(128)
gemv_kernel(const float* __restrict__ W, const float* __restrict__ bias,
            float* __restrict__ out) {
    __shared__ __align__(16) float ssig[D_MODEL];

    const int tid = threadIdx.x;
#pragma unroll
    for (int i = tid; i < D_MODEL / 4; i += 128)
        ((float4*)ssig)[i] = ((const float4*)g_signal)[i];
    __syncthreads();

    const int warp = tid >> 5;
    const int lane = tid & 31;
    const int row  = blockIdx.x * 4 + warp;

    const float4* w4 = (const float4*)(W + row * D_MODEL);
    float acc = 0.0f;
#pragma unroll
    for (int kk = lane; kk < D_MODEL / 4; kk += 32) {
        float4 wv = w4[kk];
        float4 sv = ((const float4*)ssig)[kk];
        acc = fmaf(wv.x, sv.x, acc);
        acc = fmaf(wv.y, sv.y, acc);
        acc = fmaf(wv.z, sv.z, acc);
        acc = fmaf(wv.w, sv.w, acc);
    }
#pragma unroll
    for (int off = 16; off > 0; off >>= 1)
        acc += __shfl_down_sync(0xffffffffu, acc, off);

    if (lane == 0) out[row] = acc + bias[row];
}

// ---------------------------------------------------------------------------
extern "C" void kernel_launch(void* const* d_in, const int* in_sizes, int n_in,
                              void* d_out, int out_size) {
    const float* inputs = (const float*)d_in[0];   // [32768]
    const float* W      = (const float*)d_in[1];   // [1024,1024]
    const float* b      = (const float*)d_in[2];   // [1024]
    float*       out    = (float*)d_out;           // [1024]

    sinsum_kernel<<<NBLK_A, 128>>>(inputs);
    reduce_kernel<<<128, 256>>>();
    gemv_kernel<<<D_MODEL / 4, 128>>>(W, b, out);
    (void)in_sizes; (void)n_in; (void)out_size;
}

// round 17
// speedup vs baseline: 1.9924x; 1.0227x over previous
#include <cuda_runtime.h>
#include <math.h>

#define D_MODEL   1024
#define SEQ_LEN   32768
#define NBLK_A    1024                  // phase-A blocks (128 thr each)
#define LPB       32                    // l's per block
#define LPW       8                     // l's per warp (4 warps/block)

#define TWO_PI    6.283185307179586f
#define INV_2PI   0.15915494309189535f
#define MAGIC     12582912.0f           // 1.5 * 2^23
#define C1_2PI    6.28318548202514648f  // fl32(2*pi)
#define INV1023   (1.0f / 1023.0f)

typedef unsigned long long ull;

// Scratch (device globals; no allocation in kernel_launch)
// g_part[slice][col]; col i = m*32+k packs d=(32k+2m, 32k+2m+1),
// sign-twisted by sigma_m. A stores coalesced (STG.64).
__device__ ull g_part[NBLK_A * 512];               // 4 MB
__device__ __align__(16) float g_signal[D_MODEL];

// ---------------- packed f32x2 helpers --------------------------------------
__device__ __forceinline__ ull fma2(ull a, ull b, ull c) {
    ull d; asm("fma.rn.f32x2 %0,%1,%2,%3;" : "=l"(d) : "l"(a), "l"(b), "l"(c)); return d;
}
__device__ __forceinline__ ull add2(ull a, ull b) {
    ull d; asm("add.rn.f32x2 %0,%1,%2;" : "=l"(d) : "l"(a), "l"(b)); return d;
}
__device__ __forceinline__ ull pk2(float lo, float hi) {
    ull d; asm("mov.b64 %0,{%1,%2};" : "=l"(d) : "f"(lo), "f"(hi)); return d;
}
__device__ __forceinline__ float2 unpk(ull v) {
    float2 r; asm("mov.b64 {%0,%1},%2;" : "=f"(r.x), "=f"(r.y) : "l"(v)); return r;
}

// ---------------------------------------------------------------------------
// Kernel A: packed-pair Chebyshev recurrence over d, TWO interleaved l-chains
// per iteration. Lane k owns d=32k..32k+31 as 16 packed pairs. (R16 verbatim.)
// ---------------------------------------------------------------------------
__global__ void __launch_bounds__(128, 8)
sinsum_kernel(const float* __restrict__ inputs) {
    __shared__ float4 co[LPB];        // (a, a*log1p(l), 2cos(dl), 2cos(2dl))
    __shared__ ull    sred[2 * 512];  // 8KB two-phase epilogue buffer

    const int tid = threadIdx.x;
    const int w   = tid >> 5;         // 0..3
    const int k   = tid & 31;

    if (tid < LPB) {
        const int l = blockIdx.x * LPB + tid;
        float x  = inputs[l];
        float a  = TWO_PI * x;
        float p  = log1pf((float)l);
        float dl = a * INV1023;
        float d2 = dl * dl;
        float u2 = 4.0f * d2;                         // (2*dl)^2
        float c  = fmaf(d2, fmaf(d2, fmaf(d2, -(1.0f/360.0f), (1.0f/12.0f)), -1.0f), 2.0f);
        float c2 = fmaf(u2, fmaf(u2, fmaf(u2, -(1.0f/360.0f), (1.0f/12.0f)), -1.0f), 2.0f);
        co[tid]  = make_float4(a, a * p, c, c2);
    }
    __syncthreads();

    const float tk = (float)(32 * k) * INV1023;

    ull acc[16];
#pragma unroll
    for (int m = 0; m < 16; ++m) acc[m] = 0ull;

#pragma unroll 1
    for (int jp = 0; jp < LPW / 2; ++jp) {
        float4 CA = co[w * LPW + 2 * jp];
        float4 CB = co[w * LPW + 2 * jp + 1];

        // --- seeds for chain A and chain B (independent) ---
        float phiA = fmaf(CA.x, tk, CA.y);
        float phiB = fmaf(CB.x, tk, CB.y);
        float yA   = fmaf(phiA, INV_2PI, MAGIC);
        float yB   = fmaf(phiB, INV_2PI, MAGIC);
        float rA   = fmaf(yA - MAGIC, -C1_2PI, phiA);
        float rB   = fmaf(yB - MAGIC, -C1_2PI, phiB);
        float dlA  = CA.x * INV1023;
        float dlB  = CB.x * INV1023;
        float sA0  = __sinf(rA);
        float sB0  = __sinf(rB);
        float sA1  = __sinf(rA + dlA);
        float sB1  = __sinf(rB + dlB);
        float sA2  = fmaf(CA.z, sA1, -sA0);
        float sB2  = fmaf(CB.z, sB1, -sB0);
        float sA3  = fmaf(CA.z, sA2, -sA1);
        float sB3  = fmaf(CB.z, sB2, -sB1);

        ull a0 = pk2(sA0, sA1), a1 = pk2(sA2, sA3);
        ull b0 = pk2(sB0, sB1), b1 = pk2(sB2, sB3);
        ull cAp = pk2(CA.w, CA.w), cAn = pk2(-CA.w, -CA.w);
        ull cBp = pk2(CB.w, CB.w), cBn = pk2(-CB.w, -CB.w);

        acc[0] = add2(acc[0], add2(a0, b0));
        acc[1] = add2(acc[1], add2(a1, b1));

#pragma unroll
        for (int m = 2; m < 16; ++m) {
            // sign-twisted: a_m = fma2(m odd ? +c2 : -c2, a_{m-1}, a_{m-2})
            ull an = fma2((m & 1) ? cAp : cAn, a1, a0);
            ull bn = fma2((m & 1) ? cBp : cBn, b1, b0);
            acc[m] = add2(acc[m], add2(an, bn));
            a0 = a1; a1 = an;
            b0 = b1; b1 = bn;
        }
    }

    // Epilogue phase 1: warps 2,3 stage.
    if (w >= 2) {
#pragma unroll
        for (int m = 0; m < 16; ++m)
            sred[(w - 2) * 512 + m * 32 + k] = acc[m];
    }
    __syncthreads();
    // Phase 2: warps 0,1 add in place.
    if (w < 2) {
#pragma unroll
        for (int m = 0; m < 16; ++m) {
            const int i = w * 512 + m * 32 + k;
            sred[i] = add2(sred[i], acc[m]);
        }
    }
    __syncthreads();

    // Gather 2 segments, coalesced store.
#pragma unroll
    for (int rep = 0; rep < 4; ++rep) {
        const int i = tid + rep * 128;
        ull s = add2(sred[i], sred[512 + i]);
        g_part[blockIdx.x * 512 + i] = s;             // STG.64 coalesced
    }
}

// ---------------------------------------------------------------------------
// Kernel B: PDL secondary. Grid-sync on A, then reduce 1024 slices per
// packed column. 128 blocks x 256 threads (R16 body).
// ---------------------------------------------------------------------------
__global__ void __launch_bounds__(256)
reduce_kernel() {
    __shared__ ull sm[256];
    const int tid = threadIdx.x;
    const int b   = blockIdx.x;
    const int sp  = tid >> 2;
    const int c   = tid & 3;
    const int col = 4 * b + c;

    cudaGridDependencySynchronize();   // wait for A's g_part

    ull s = 0ull;
#pragma unroll
    for (int j = 0; j < 16; ++j)
        s = add2(s, g_part[(sp + 64 * j) * 512 + col]);
    sm[tid] = s;
    __syncthreads();

#pragma unroll
    for (int step = 128; step >= 4; step >>= 1) {
        if (tid < step)
            sm[tid] = add2(sm[tid], sm[tid + step]);
        __syncthreads();
    }

    if (tid < 4) {
        const int cc = 4 * b + tid;
        const int m  = cc >> 5;
        const int kk = cc & 31;
        const float sg = ((m >> 1) & 1) ? -1.0f : 1.0f;   // undo sigma_m
        float2 v = unpk(sm[tid]);
        const int d0 = 32 * kk + 2 * m;
        g_signal[d0]     = sg * v.x;
        g_signal[d0 + 1] = sg * v.y;
    }
}

// ---------------------------------------------------------------------------
// Kernel C: PDL secondary. Preload W into registers BEFORE grid-sync
// (overlaps 4MB W stream with A/B execution), then sync, then GEMV.
// 256 blocks x 128 threads, warp per row.
// ---------------------------------------------------------------------------
__global__ void __launch_bounds__(128)
gemv_kernel(const float* __restrict__ W, const float* __restrict__ bias,
            float* __restrict__ out) {
    __shared__ __align__(16) float ssig[D_MODEL];

    const int tid  = threadIdx.x;
    const int warp = tid >> 5;
    const int lane = tid & 31;
    const int row  = blockIdx.x * 4 + warp;

    // W preload: independent of A/B -> issue before the dependency sync.
    const float4* w4 = (const float4*)(W + row * D_MODEL);
    float4 wv[8];
#pragma unroll
    for (int j = 0; j < 8; ++j)
        wv[j] = w4[lane + 32 * j];
    float bb = bias[row];

    cudaGridDependencySynchronize();   // wait for B's g_signal

#pragma unroll
    for (int i = tid; i < D_MODEL / 4; i += 128)
        ((float4*)ssig)[i] = ((const float4*)g_signal)[i];
    __syncthreads();

    float acc = 0.0f;
#pragma unroll
    for (int j = 0; j < 8; ++j) {
        float4 sv = ((const float4*)ssig)[lane + 32 * j];
        acc = fmaf(wv[j].x, sv.x, acc);
        acc = fmaf(wv[j].y, sv.y, acc);
        acc = fmaf(wv[j].z, sv.z, acc);
        acc = fmaf(wv[j].w, sv.w, acc);
    }
#pragma unroll
    for (int off = 16; off > 0; off >>= 1)
        acc += __shfl_down_sync(0xffffffffu, acc, off);

    if (lane == 0) out[row] = acc + bb;
}

// ---------------------------------------------------------------------------
extern "C" void kernel_launch(void* const* d_in, const int* in_sizes, int n_in,
                              void* d_out, int out_size) {
    const float* inputs = (const float*)d_in[0];   // [32768]
    const float* W      = (const float*)d_in[1];   // [1024,1024]
    const float* b      = (const float*)d_in[2];   // [1024]
    float*       out    = (float*)d_out;           // [1024]

    sinsum_kernel<<<NBLK_A, 128>>>(inputs);

    cudaLaunchAttribute attr[1];
    attr[0].id = cudaLaunchAttributeProgrammaticStreamSerialization;
    attr[0].val.programmaticStreamSerializationAllowed = 1;

    {   // B with PDL
        cudaLaunchConfig_t cfg = {};
        cfg.gridDim  = dim3(128, 1, 1);
        cfg.blockDim = dim3(256, 1, 1);
        cfg.stream   = 0;
        cfg.attrs    = attr;
        cfg.numAttrs = 1;
        cudaLaunchKernelEx(&cfg, reduce_kernel);
    }
    {   // C with PDL
        cudaLaunchConfig_t cfg = {};
        cfg.gridDim  = dim3(D_MODEL / 4, 1, 1);
        cfg.blockDim = dim3(128, 1, 1);
        cfg.stream   = 0;
        cfg.attrs    = attr;
        cfg.numAttrs = 1;
        cudaLaunchKernelEx(&cfg, gemv_kernel, W, b, out);
    }
    (void)in_sizes; (void)n_in; (void)out_size;
}